// round 16
// baseline (speedup 1.0000x reference)
#include <cuda_runtime.h>
#include <cuda_bf16.h>
#include <cuda_fp16.h>
#include <mma.h>
#include <math.h>
#include <cstdint>

using namespace nvcuda;

#define NN 10000
#define NP 10112
#define EE 160000
#define ECHUNK 16000   // edges per L2-resident fused chunk (32.75 MB)

// ---------------- device scratch ----------------
__device__ __half g_proj1h[NP * 256];
__device__ float g_ssrc1[NN * 2];
__device__ float g_strg1[NN * 2];
__device__ __half g_hh[NP * 512];
__device__ __half g_w2h[512 * 512];
__device__ __half g_proj2h[NP * 512];
__device__ float g_ssrc2[NN * 4];
__device__ float g_strg2[NN * 4];
__device__ __nv_bfloat16 g_out2h[NP * 128];
__device__ __nv_bfloat16 g_PQh[NP * 2048];
__device__ __nv_bfloat16 g_wacad[128 * 2048];
__device__ __nv_bfloat16 g_wib_h[128 * 1024];
__device__ __nv_bfloat16 g_wf1_h[1024 * 512];
__device__ __nv_bfloat16 g_msh[EE * 128];
__device__ __nv_bfloat16 g_fused[(size_t)ECHUNK * 1024];  // ONE chunk, reused (L2-hot)
__device__ float g_logit[EE];
// edge sort (by target)
__device__ int g_deg[NN];
__device__ int g_off[NN + 1];
__device__ int g_cur[NN];
__device__ int g_srt[EE];

__device__ __forceinline__ float eluf(float v) { return v > 0.f ? v : expm1f(v); }

__device__ __forceinline__ uint32_t smem_u32(const void* p) {
    uint32_t a;
    asm("{ .reg .u64 t; cvta.to.shared.u64 t, %1; cvt.u32.u64 %0, t; }" : "=r"(a) : "l"(p));
    return a;
}
__device__ __forceinline__ void cpa16(uint32_t saddr, const void* g) {
    asm volatile("cp.async.cg.shared.global [%0], [%1], 16;" :: "r"(saddr), "l"(g));
}
__device__ __forceinline__ void cpa16p(uint32_t saddr, const void* g, bool pred) {
    int sz = pred ? 16 : 0;
    asm volatile("cp.async.cg.shared.global [%0], [%1], 16, %2;"
                 :: "r"(saddr), "l"(g), "r"(sz));
}
#define CP_COMMIT() asm volatile("cp.async.commit_group;" ::: "memory")
#define CP_WAIT0()  asm volatile("cp.async.wait_group 0;" ::: "memory")
#define CP_WAIT1()  asm volatile("cp.async.wait_group 1;" ::: "memory")

// ---------------- init ----------------
__global__ void k_init() {
    int i = blockIdx.x * blockDim.x + threadIdx.x;
    int stride = gridDim.x * blockDim.x;
    for (int j = i; j < EE; j += stride) g_logit[j] = 0.f;
    for (int j = i; j < NN; j += stride) g_deg[j] = 0;
}

// ---------------- edge sort by target ----------------
__global__ void k_hist(const int* __restrict__ ei) {
    int i = blockIdx.x * blockDim.x + threadIdx.x;
    if (i < EE) atomicAdd(&g_deg[ei[EE + i]], 1);
}

__global__ void k_scan() {
    __shared__ int ps[1024];
    int tid = threadIdx.x;
    int base = tid * 10;
    int local[10];
    int s = 0;
#pragma unroll
    for (int k = 0; k < 10; k++) {
        int idx = base + k;
        local[k] = s;
        if (idx < NN) s += g_deg[idx];
    }
    ps[tid] = s;
    __syncthreads();
    for (int o = 1; o < 1024; o <<= 1) {
        int v = (tid >= o) ? ps[tid - o] : 0;
        __syncthreads();
        ps[tid] += v;
        __syncthreads();
    }
    int pre = (tid == 0) ? 0 : ps[tid - 1];
#pragma unroll
    for (int k = 0; k < 10; k++) {
        int idx = base + k;
        if (idx < NN) { g_off[idx] = pre + local[k]; g_cur[idx] = pre + local[k]; }
    }
    if (tid == 1023) g_off[NN] = ps[1023];
}

__global__ void k_sortE(const int* __restrict__ ei) {
    int i = blockIdx.x * blockDim.x + threadIdx.x;
    if (i >= EE) return;
    int t = ei[EE + i];
    int p = atomicAdd(&g_cur[t], 1);
    g_srt[p] = ei[i];
}

// ====== tf32 GEMM, fp16 output — layer-1 projection =========================
template <int K, int COLS>
__global__ __launch_bounds__(256) void k_gemm_tf32h(const float* __restrict__ A,
                                                    const float* __restrict__ W,
                                                    __half* __restrict__ C) {
    constexpr int KC = 32;
    constexpr int NSTG = K / KC;
    extern __shared__ float smf[];
    float* As = smf;
    float* Ws = smf + 2 * 128 * 36;
    uint32_t asb = smem_u32(As), wsb = smem_u32(Ws);
    int m0 = blockIdx.x * 128, n0 = blockIdx.y * 128;
    int tid = threadIdx.x, w = tid >> 5, lane = tid & 31;
    int wm = w & 1, wn = w >> 1;

    auto stage = [&](int s) {
        int kc = s * KC, buf = s & 1;
#pragma unroll
        for (int i = tid; i < 1024; i += 256) {
            int r = i >> 3, c = (i & 7) * 4;
            int gm = m0 + r;
            const float* src = (gm < NN) ? (A + (size_t)gm * K + kc + c) : A;
            cpa16p(asb + (uint32_t)((buf * 128 + r) * 36 + c) * 4, src, gm < NN);
        }
#pragma unroll
        for (int i = tid; i < 1024; i += 256) {
            int r = i >> 5, c = (i & 31) * 4;
            cpa16(wsb + (uint32_t)((buf * 32 + r) * 132 + c) * 4,
                  W + (size_t)(kc + r) * COLS + n0 + c);
        }
    };

    wmma::fragment<wmma::accumulator, 16, 16, 8, float> acc[4][2];
#pragma unroll
    for (int mt = 0; mt < 4; mt++)
#pragma unroll
        for (int nt = 0; nt < 2; nt++) wmma::fill_fragment(acc[mt][nt], 0.f);

    stage(0); CP_COMMIT();
    for (int s = 0; s < NSTG; s++) {
        if (s + 1 < NSTG) { stage(s + 1); CP_COMMIT(); CP_WAIT1(); }
        else { CP_WAIT0(); }
        __syncthreads();
        const float* Ab = As + (s & 1) * 128 * 36;
        const float* Wb = Ws + (s & 1) * 32 * 132;
#pragma unroll
        for (int k8 = 0; k8 < KC / 8; k8++) {
            wmma::fragment<wmma::matrix_a, 16, 16, 8, wmma::precision::tf32,
                           wmma::row_major> a[4];
#pragma unroll
            for (int mt = 0; mt < 4; mt++)
                wmma::load_matrix_sync(a[mt], Ab + (wm * 64 + mt * 16) * 36 + k8 * 8, 36);
#pragma unroll
            for (int nt = 0; nt < 2; nt++) {
                wmma::fragment<wmma::matrix_b, 16, 16, 8, wmma::precision::tf32,
                               wmma::row_major> b;
                wmma::load_matrix_sync(b, Wb + (k8 * 8) * 132 + wn * 32 + nt * 16, 132);
#pragma unroll
                for (int mt = 0; mt < 4; mt++)
                    wmma::mma_sync(acc[mt][nt], a[mt], b, acc[mt][nt]);
            }
        }
        __syncthreads();
    }
    float* scratch = As + w * 256;
#pragma unroll
    for (int mt = 0; mt < 4; mt++)
#pragma unroll
        for (int nt = 0; nt < 2; nt++) {
            wmma::store_matrix_sync(scratch, acc[mt][nt], 16, wmma::mem_row_major);
            __syncwarp();
            int row = lane >> 1, colb = (lane & 1) * 8;
            const float* sp = scratch + row * 16 + colb;
            int gm = m0 + wm * 64 + mt * 16 + row;
            __half* dst = C + (size_t)gm * COLS + n0 + wn * 32 + nt * 16 + colb;
            uint4 o;
            __half2 t;
            t = __floats2half2_rn(sp[0], sp[1]); o.x = *(uint32_t*)&t;
            t = __floats2half2_rn(sp[2], sp[3]); o.y = *(uint32_t*)&t;
            t = __floats2half2_rn(sp[4], sp[5]); o.z = *(uint32_t*)&t;
            t = __floats2half2_rn(sp[6], sp[7]); o.w = *(uint32_t*)&t;
            *(uint4*)dst = o;
            __syncwarp();
        }
}
#define TF32_SMEM ((2 * 128 * 36 + 2 * 32 * 132) * 4)

// ====== fp16 GEMM — layer-2 projection ======================================
template <int K, int COLS>
__global__ __launch_bounds__(256) void k_gemm_fp16(const __half* __restrict__ A,
                                                   const __half* __restrict__ W,
                                                   __half* __restrict__ C) {
    constexpr int KC = 32;
    constexpr int NSTG = K / KC;
    __shared__ __half As[2][128][40];
    __shared__ __half Ws[2][KC][136];
    uint32_t asb = smem_u32(&As[0][0][0]), wsb = smem_u32(&Ws[0][0][0]);
    int m0 = blockIdx.x * 128, n0 = blockIdx.y * 128;
    int tid = threadIdx.x, w = tid >> 5, lane = tid & 31;
    int wm = w & 1, wn = w >> 1;

    auto stage = [&](int s) {
        int kc = s * KC, buf = s & 1;
#pragma unroll
        for (int i = tid; i < 512; i += 256) {
            int r = i >> 2, c = (i & 3) * 8;
            cpa16(asb + (uint32_t)((buf * 128 + r) * 40 + c) * 2,
                  A + (size_t)(m0 + r) * K + kc + c);
        }
#pragma unroll
        for (int i = tid; i < 512; i += 256) {
            int r = i >> 4, c = (i & 15) * 8;
            cpa16(wsb + (uint32_t)((buf * KC + r) * 136 + c) * 2,
                  W + (size_t)(kc + r) * COLS + n0 + c);
        }
    };

    wmma::fragment<wmma::accumulator, 16, 16, 16, float> acc[4][2];
#pragma unroll
    for (int mt = 0; mt < 4; mt++)
#pragma unroll
        for (int nt = 0; nt < 2; nt++) wmma::fill_fragment(acc[mt][nt], 0.f);

    stage(0); CP_COMMIT();
    for (int s = 0; s < NSTG; s++) {
        if (s + 1 < NSTG) { stage(s + 1); CP_COMMIT(); CP_WAIT1(); }
        else { CP_WAIT0(); }
        __syncthreads();
        const __half* Ab = &As[s & 1][0][0];
        const __half* Wb = &Ws[s & 1][0][0];
#pragma unroll
        for (int k16 = 0; k16 < KC / 16; k16++) {
            wmma::fragment<wmma::matrix_a, 16, 16, 16, __half, wmma::row_major> a[4];
#pragma unroll
            for (int mt = 0; mt < 4; mt++)
                wmma::load_matrix_sync(a[mt], Ab + (wm * 64 + mt * 16) * 40 + k16 * 16, 40);
#pragma unroll
            for (int nt = 0; nt < 2; nt++) {
                wmma::fragment<wmma::matrix_b, 16, 16, 16, __half, wmma::row_major> b;
                wmma::load_matrix_sync(b, Wb + (k16 * 16) * 136 + wn * 32 + nt * 16, 136);
#pragma unroll
                for (int mt = 0; mt < 4; mt++)
                    wmma::mma_sync(acc[mt][nt], a[mt], b, acc[mt][nt]);
            }
        }
        __syncthreads();
    }
    float* scratch = (float*)(&As[0][0][0]) + w * 256;
#pragma unroll
    for (int mt = 0; mt < 4; mt++)
#pragma unroll
        for (int nt = 0; nt < 2; nt++) {
            wmma::store_matrix_sync(scratch, acc[mt][nt], 16, wmma::mem_row_major);
            __syncwarp();
            int row = lane >> 1, colb = (lane & 1) * 8;
            const float* sp = scratch + row * 16 + colb;
            int gm = m0 + wm * 64 + mt * 16 + row;
            __half* dst = C + (size_t)gm * COLS + n0 + wn * 32 + nt * 16 + colb;
            uint4 o;
            __half2 t;
            t = __floats2half2_rn(sp[0], sp[1]); o.x = *(uint32_t*)&t;
            t = __floats2half2_rn(sp[2], sp[3]); o.y = *(uint32_t*)&t;
            t = __floats2half2_rn(sp[4], sp[5]); o.z = *(uint32_t*)&t;
            t = __floats2half2_rn(sp[6], sp[7]); o.w = *(uint32_t*)&t;
            *(uint4*)dst = o;
            __syncwarp();
        }
}

// ====== bf16 GEMM — for P|Q =================================================
template <int K, int COLS>
__global__ __launch_bounds__(256) void k_gemm_bf16h(const __nv_bfloat16* __restrict__ A,
                                                    const __nv_bfloat16* __restrict__ W,
                                                    __nv_bfloat16* __restrict__ C) {
    constexpr int KC = 32;
    constexpr int NSTG = K / KC;
    __shared__ __nv_bfloat16 As[2][128][40];
    __shared__ __nv_bfloat16 Ws[2][KC][136];
    uint32_t asb = smem_u32(&As[0][0][0]), wsb = smem_u32(&Ws[0][0][0]);
    int m0 = blockIdx.x * 128, n0 = blockIdx.y * 128;
    int tid = threadIdx.x, w = tid >> 5, lane = tid & 31;
    int wm = w & 1, wn = w >> 1;

    auto stage = [&](int s) {
        int kc = s * KC, buf = s & 1;
#pragma unroll
        for (int i = tid; i < 512; i += 256) {
            int r = i >> 2, c = (i & 3) * 8;
            cpa16(asb + (uint32_t)((buf * 128 + r) * 40 + c) * 2,
                  A + (size_t)(m0 + r) * K + kc + c);
        }
#pragma unroll
        for (int i = tid; i < 512; i += 256) {
            int r = i >> 4, c = (i & 15) * 8;
            cpa16(wsb + (uint32_t)((buf * KC + r) * 136 + c) * 2,
                  W + (size_t)(kc + r) * COLS + n0 + c);
        }
    };

    wmma::fragment<wmma::accumulator, 16, 16, 16, float> acc[4][2];
#pragma unroll
    for (int mt = 0; mt < 4; mt++)
#pragma unroll
        for (int nt = 0; nt < 2; nt++) wmma::fill_fragment(acc[mt][nt], 0.f);

    stage(0); CP_COMMIT();
    for (int s = 0; s < NSTG; s++) {
        if (s + 1 < NSTG) { stage(s + 1); CP_COMMIT(); CP_WAIT1(); }
        else { CP_WAIT0(); }
        __syncthreads();
        const __nv_bfloat16* Ab = &As[s & 1][0][0];
        const __nv_bfloat16* Wb = &Ws[s & 1][0][0];
#pragma unroll
        for (int k16 = 0; k16 < KC / 16; k16++) {
            wmma::fragment<wmma::matrix_a, 16, 16, 16, __nv_bfloat16, wmma::row_major> a[4];
#pragma unroll
            for (int mt = 0; mt < 4; mt++)
                wmma::load_matrix_sync(a[mt], Ab + (wm * 64 + mt * 16) * 40 + k16 * 16, 40);
#pragma unroll
            for (int nt = 0; nt < 2; nt++) {
                wmma::fragment<wmma::matrix_b, 16, 16, 16, __nv_bfloat16, wmma::row_major> b;
                wmma::load_matrix_sync(b, Wb + (k16 * 16) * 136 + wn * 32 + nt * 16, 136);
#pragma unroll
                for (int mt = 0; mt < 4; mt++)
                    wmma::mma_sync(acc[mt][nt], a[mt], b, acc[mt][nt]);
            }
        }
        __syncthreads();
    }
    float* scratch = (float*)(&As[0][0][0]) + w * 256;
#pragma unroll
    for (int mt = 0; mt < 4; mt++)
#pragma unroll
        for (int nt = 0; nt < 2; nt++) {
            wmma::store_matrix_sync(scratch, acc[mt][nt], 16, wmma::mem_row_major);
            __syncwarp();
            int row = lane >> 1, colb = (lane & 1) * 8;
            const float* sp = scratch + row * 16 + colb;
            int gm = m0 + wm * 64 + mt * 16 + row;
            __nv_bfloat16* dst = C + (size_t)gm * COLS + n0 + wn * 32 + nt * 16 + colb;
            uint4 o;
            __nv_bfloat162 t;
            t = __floats2bfloat162_rn(sp[0], sp[1]); o.x = *(uint32_t*)&t;
            t = __floats2bfloat162_rn(sp[2], sp[3]); o.y = *(uint32_t*)&t;
            t = __floats2bfloat162_rn(sp[4], sp[5]); o.z = *(uint32_t*)&t;
            t = __floats2bfloat162_rn(sp[6], sp[7]); o.w = *(uint32_t*)&t;
            *(uint4*)dst = o;
            __syncwarp();
        }
}

// ---------------- attention score projections (fp16 proj) ----------------
template <int H>
__global__ void k_scores(const __half* __restrict__ proj, const float* __restrict__ asrc,
                         const float* __restrict__ atrg, float* __restrict__ ssrc,
                         float* __restrict__ strg) {
    int n = blockIdx.x;
    int h = threadIdx.x >> 5, lane = threadIdx.x & 31;
    uint2 pu = *(const uint2*)(proj + ((size_t)n * H + h) * 128 + lane * 4);
    float2 p01 = __half22float2(*(__half2*)&pu.x);
    float2 p23 = __half22float2(*(__half2*)&pu.y);
    float4 a = *(const float4*)(asrc + h * 128 + lane * 4);
    float4 b = *(const float4*)(atrg + h * 128 + lane * 4);
    float ps = p01.x * a.x + p01.y * a.y + p23.x * a.z + p23.y * a.w;
    float pt = p01.x * b.x + p01.y * b.y + p23.x * b.z + p23.y * b.w;
#pragma unroll
    for (int o = 16; o > 0; o >>= 1) {
        ps += __shfl_down_sync(0xffffffffu, ps, o);
        pt += __shfl_down_sync(0xffffffffu, pt, o);
    }
    if (lane == 0) { ssrc[n * H + h] = ps; strg[n * H + h] = pt; }
}

// ===== gather-side aggregation, layer 1 (H=2) + finalize1 fused ==============
__global__ __launch_bounds__(256) void k_agg1(
    const float* __restrict__ ss, const float* __restrict__ st,
    const __half* __restrict__ proj, const float* __restrict__ local_emb,
    const float* __restrict__ b1, __half* __restrict__ hbuf) {
    int t = blockIdx.x * 8 + (threadIdx.x >> 5);
    int lane = threadIdx.x & 31;
    if (t >= NN) return;
    float st0 = st[t * 2], st1 = st[t * 2 + 1];
    float a0[4] = {0.f, 0.f, 0.f, 0.f}, a1[4] = {0.f, 0.f, 0.f, 0.f};
    float d0 = 0.f, d1 = 0.f;
    int jb = g_off[t], je = g_off[t + 1];
    for (int j = jb; j < je; j++) {
        int s = __ldg(&g_srt[j]);
        float v0 = __ldg(&ss[s * 2]) + st0;
        float v1 = __ldg(&ss[s * 2 + 1]) + st1;
        v0 = v0 > 0.f ? v0 : 0.2f * v0;
        v1 = v1 > 0.f ? v1 : 0.2f * v1;
        float e0 = expf(v0), e1 = expf(v1);
        d0 += e0; d1 += e1;
        uint2 p0 = *(const uint2*)(proj + (size_t)s * 256 + lane * 4);
        uint2 p1 = *(const uint2*)(proj + (size_t)s * 256 + 128 + lane * 4);
        float2 x01 = __half22float2(*(__half2*)&p0.x);
        float2 x23 = __half22float2(*(__half2*)&p0.y);
        a0[0] += e0 * x01.x; a0[1] += e0 * x01.y;
        a0[2] += e0 * x23.x; a0[3] += e0 * x23.y;
        float2 y01 = __half22float2(*(__half2*)&p1.x);
        float2 y23 = __half22float2(*(__half2*)&p1.y);
        a1[0] += e1 * y01.x; a1[1] += e1 * y01.y;
        a1[2] += e1 * y23.x; a1[3] += e1 * y23.y;
    }
    float i0 = 1.f / (d0 + 1e-16f), i1 = 1.f / (d1 + 1e-16f);
    int c = lane * 4;
    float4 le = *(const float4*)(local_emb + (size_t)t * 128 + c);
    {
        float4 bv = *(const float4*)(b1 + c);
        __half2 o0 = __floats2half2_rn(eluf(a0[0] * i0 + bv.x), eluf(a0[1] * i0 + bv.y));
        __half2 o1 = __floats2half2_rn(eluf(a0[2] * i0 + bv.z), eluf(a0[3] * i0 + bv.w));
        uint2 o = {*(uint32_t*)&o0, *(uint32_t*)&o1};
        *(uint2*)(hbuf + (size_t)t * 512 + c) = o;
        float4 bl = *(const float4*)(b1 + 128 + c);
        o0 = __floats2half2_rn(eluf(le.x + bl.x), eluf(le.y + bl.y));
        o1 = __floats2half2_rn(eluf(le.z + bl.z), eluf(le.w + bl.w));
        uint2 ol = {*(uint32_t*)&o0, *(uint32_t*)&o1};
        *(uint2*)(hbuf + (size_t)t * 512 + 128 + c) = ol;
    }
    {
        float4 bv = *(const float4*)(b1 + 256 + c);
        __half2 o0 = __floats2half2_rn(eluf(a1[0] * i1 + bv.x), eluf(a1[1] * i1 + bv.y));
        __half2 o1 = __floats2half2_rn(eluf(a1[2] * i1 + bv.z), eluf(a1[3] * i1 + bv.w));
        uint2 o = {*(uint32_t*)&o0, *(uint32_t*)&o1};
        *(uint2*)(hbuf + (size_t)t * 512 + 256 + c) = o;
        float4 bl = *(const float4*)(b1 + 384 + c);
        o0 = __floats2half2_rn(eluf(le.x + bl.x), eluf(le.y + bl.y));
        o1 = __floats2half2_rn(eluf(le.z + bl.z), eluf(le.w + bl.w));
        uint2 ol = {*(uint32_t*)&o0, *(uint32_t*)&o1};
        *(uint2*)(hbuf + (size_t)t * 512 + 384 + c) = ol;
    }
}

// ===== gather-side aggregation, layer 2 (H=4, mean) + finalize2 fused ========
__global__ __launch_bounds__(256) void k_agg2(
    const float* __restrict__ ss, const float* __restrict__ st,
    const __half* __restrict__ proj, const float* __restrict__ b2,
    __nv_bfloat16* __restrict__ out2h) {
    int t = blockIdx.x * 8 + (threadIdx.x >> 5);
    int lane = threadIdx.x & 31;
    if (t >= NN) return;
    float sth[4];
#pragma unroll
    for (int h = 0; h < 4; h++) sth[h] = st[t * 4 + h];
    float acc[4][4];
#pragma unroll
    for (int h = 0; h < 4; h++)
#pragma unroll
        for (int k = 0; k < 4; k++) acc[h][k] = 0.f;
    float den[4] = {0.f, 0.f, 0.f, 0.f};
    int jb = g_off[t], je = g_off[t + 1];
    for (int j = jb; j < je; j++) {
        int s = __ldg(&g_srt[j]);
#pragma unroll
        for (int h = 0; h < 4; h++) {
            float v = __ldg(&ss[s * 4 + h]) + sth[h];
            v = v > 0.f ? v : 0.2f * v;
            float e = expf(v);
            den[h] += e;
            uint2 pu = *(const uint2*)(proj + (size_t)s * 512 + h * 128 + lane * 4);
            float2 x01 = __half22float2(*(__half2*)&pu.x);
            float2 x23 = __half22float2(*(__half2*)&pu.y);
            acc[h][0] += e * x01.x; acc[h][1] += e * x01.y;
            acc[h][2] += e * x23.x; acc[h][3] += e * x23.y;
        }
    }
    float inv[4];
#pragma unroll
    for (int h = 0; h < 4; h++) inv[h] = 1.f / (den[h] + 1e-16f);
    int f = lane * 4;
    float4 bv = *(const float4*)(b2 + f);
    float r[4];
#pragma unroll
    for (int k = 0; k < 4; k++) {
        float v = acc[0][k] * inv[0] + acc[1][k] * inv[1] +
                  acc[2][k] * inv[2] + acc[3][k] * inv[3];
        float bb = (k == 0) ? bv.x : (k == 1) ? bv.y : (k == 2) ? bv.z : bv.w;
        r[k] = eluf(0.25f * v + bb);
    }
    __nv_bfloat162 o0 = __floats2bfloat162_rn(r[0], r[1]);
    __nv_bfloat162 o1 = __floats2bfloat162_rn(r[2], r[3]);
    uint2 o = {*(uint32_t*)&o0, *(uint32_t*)&o1};
    *(uint2*)(out2h + (size_t)t * 128 + f) = o;
}

// ---------------- MLP weight prep ----------------
__global__ void k_wprep(const float* __restrict__ Wi, __nv_bfloat16* __restrict__ wacad,
                        __nv_bfloat16* __restrict__ wibh) {
    int i = blockIdx.x * blockDim.x + threadIdx.x;
    if (i >= 128 * 2048) return;
    int k = i >> 11, j = i & 2047;
    float v;
    if (j < 1024)
        v = Wi[(size_t)k * 1024 + j] + Wi[(size_t)(256 + k) * 1024 + j];
    else
        v = Wi[(size_t)k * 1024 + (j - 1024)] + Wi[(size_t)(384 + k) * 1024 + (j - 1024)];
    wacad[i] = __float2bfloat16(v);
    if (j < 1024) wibh[(size_t)k * 1024 + j] = __float2bfloat16(Wi[(size_t)(128 + k) * 1024 + j]);
}

__global__ void k_cvt_wf1(const float* __restrict__ Wf1, __nv_bfloat16* __restrict__ out) {
    int i = blockIdx.x * blockDim.x + threadIdx.x;
    if (i < 1024 * 512) out[i] = __float2bfloat16(Wf1[i]);
}

__global__ void k_cvt_w2(const float* __restrict__ W2, __half* __restrict__ out) {
    int i = blockIdx.x * blockDim.x + threadIdx.x;
    if (i < 512 * 512) out[i] = __float2half(W2[i]);
}

// ---------------- msh = bf16(e1 * e2) ----------------
__global__ void k_msh(const int* __restrict__ ei, const __nv_bfloat16* __restrict__ out2h,
                      __nv_bfloat16* __restrict__ msh) {
    int g = blockIdx.x * blockDim.x + threadIdx.x;
    int e = g >> 5, lane = g & 31;
    if (e >= EE) return;
    int s = ei[e], t = ei[EE + e];
    uint2 au = *(const uint2*)(out2h + (size_t)s * 128 + lane * 4);
    uint2 bu = *(const uint2*)(out2h + (size_t)t * 128 + lane * 4);
    uint2 o;
    *(__nv_bfloat162*)&o.x = __hmul2(*(__nv_bfloat162*)&au.x, *(__nv_bfloat162*)&bu.x);
    *(__nv_bfloat162*)&o.y = __hmul2(*(__nv_bfloat162*)&au.y, *(__nv_bfloat162*)&bu.y);
    *(uint2*)(msh + (size_t)e * 128 + lane * 4) = o;
}

// ===== k_fused: 4 warps, 64x64 warp tile; CHUNKED (fused stays in L2) =======
#define F_AS 0
#define F_BS 34816
#define F_SCR 69632
#define F_SIDX 73728
#define F_TIDX 74240
#define F_TOTAL 74752

typedef wmma::fragment<wmma::matrix_a, 16, 16, 16, __nv_bfloat16, wmma::row_major> FragA;
typedef wmma::fragment<wmma::matrix_b, 16, 16, 16, __nv_bfloat16, wmma::row_major> FragB;
typedef wmma::fragment<wmma::accumulator, 16, 16, 16, float> FragC;

__global__ __launch_bounds__(128, 2) void k_fused(
    const int* __restrict__ ei, const __nv_bfloat16* __restrict__ msh,
    const __nv_bfloat16* __restrict__ WibH, const __nv_bfloat16* __restrict__ PQh,
    const float* __restrict__ bi, __nv_bfloat16* __restrict__ fused, int ebase) {
    extern __shared__ char sm[];
    __nv_bfloat16* As = (__nv_bfloat16*)(sm + F_AS);
    __nv_bfloat16* Bs = (__nv_bfloat16*)(sm + F_BS);
    float* scr = (float*)(sm + F_SCR);
    int* sidx = (int*)(sm + F_SIDX);
    int* tidx = (int*)(sm + F_TIDX);
    uint32_t smb = smem_u32(sm);

    int tid = threadIdx.x, w = tid >> 5, lane = tid & 31;
    int n0 = blockIdx.x * 128;
    int el = blockIdx.y * 128;          // local edge base within chunk
    int e0 = ebase + el;                // global edge base
    int wm = w & 1, wn = w >> 1;

    sidx[tid] = ei[e0 + tid];
    tidx[tid] = ei[EE + e0 + tid];

#pragma unroll
    for (int i = tid; i < 2048; i += 128) {
        int r = i >> 4, c = (i & 15) * 8;
        cpa16(smb + F_AS + (uint32_t)(r * 136 + c) * 2, msh + (size_t)(e0 + r) * 128 + c);
    }
#pragma unroll
    for (int i = tid; i < 2048; i += 128) {
        int r = i >> 4, c = (i & 15) * 8;
        cpa16(smb + F_BS + (uint32_t)(r * 136 + c) * 2, WibH + (size_t)r * 1024 + n0 + c);
    }
    CP_COMMIT(); CP_WAIT0();
    __syncthreads();

    FragC acc[4][4];
#pragma unroll
    for (int mt = 0; mt < 4; mt++)
#pragma unroll
        for (int nt = 0; nt < 4; nt++) wmma::fill_fragment(acc[mt][nt], 0.f);
#pragma unroll
    for (int k16 = 0; k16 < 8; k16++) {
        FragA a[4];
#pragma unroll
        for (int mt = 0; mt < 4; mt++)
            wmma::load_matrix_sync(a[mt], As + (wm * 64 + mt * 16) * 136 + k16 * 16, 136);
#pragma unroll
        for (int nt = 0; nt < 4; nt++) {
            FragB b;
            wmma::load_matrix_sync(b, Bs + (k16 * 16) * 136 + wn * 64 + nt * 16, 136);
#pragma unroll
            for (int mt = 0; mt < 4; mt++)
                wmma::mma_sync(acc[mt][nt], a[mt], b, acc[mt][nt]);
        }
    }

    float* wscr = scr + w * 256;
    int r = lane >> 1, cb = (lane & 1) * 8;
#pragma unroll
    for (int mt = 0; mt < 4; mt++) {
#pragma unroll
        for (int nt = 0; nt < 4; nt++) {
            wmma::store_matrix_sync(wscr, acc[mt][nt], 16, wmma::mem_row_major);
            __syncwarp();
            int e = wm * 64 + mt * 16 + r;
            int jc = n0 + wn * 64 + nt * 16 + cb;
            float4 v0 = *(float4*)(wscr + r * 16 + cb);
            float4 v1 = *(float4*)(wscr + r * 16 + cb + 4);
            uint4 pu = *(const uint4*)(PQh + (size_t)sidx[e] * 2048 + jc);
            uint4 qu = *(const uint4*)(PQh + (size_t)tidx[e] * 2048 + 1024 + jc);
            float4 bi0 = *(const float4*)(bi + jc);
            float4 bi1 = *(const float4*)(bi + jc + 4);
            float2 p01 = __bfloat1622float2(*(__nv_bfloat162*)&pu.x);
            float2 p23 = __bfloat1622float2(*(__nv_bfloat162*)&pu.y);
            float2 p45 = __bfloat1622float2(*(__nv_bfloat162*)&pu.z);
            float2 p67 = __bfloat1622float2(*(__nv_bfloat162*)&pu.w);
            float2 q01 = __bfloat1622float2(*(__nv_bfloat162*)&qu.x);
            float2 q23 = __bfloat1622float2(*(__nv_bfloat162*)&qu.y);
            float2 q45 = __bfloat1622float2(*(__nv_bfloat162*)&qu.z);
            float2 q67 = __bfloat1622float2(*(__nv_bfloat162*)&qu.w);
            float r0 = fmaxf(v0.x + p01.x + q01.x + bi0.x, 0.f);
            float r1 = fmaxf(v0.y + p01.y + q01.y + bi0.y, 0.f);
            float r2 = fmaxf(v0.z + p23.x + q23.x + bi0.z, 0.f);
            float r3 = fmaxf(v0.w + p23.y + q23.y + bi0.w, 0.f);
            float r4 = fmaxf(v1.x + p45.x + q45.x + bi1.x, 0.f);
            float r5 = fmaxf(v1.y + p45.y + q45.y + bi1.y, 0.f);
            float r6 = fmaxf(v1.z + p67.x + q67.x + bi1.z, 0.f);
            float r7 = fmaxf(v1.w + p67.y + q67.y + bi1.w, 0.f);
            uint4 o;
            __nv_bfloat162 t2;
            t2 = __floats2bfloat162_rn(r0, r1); o.x = *(uint32_t*)&t2;
            t2 = __floats2bfloat162_rn(r2, r3); o.y = *(uint32_t*)&t2;
            t2 = __floats2bfloat162_rn(r4, r5); o.z = *(uint32_t*)&t2;
            t2 = __floats2bfloat162_rn(r6, r7); o.w = *(uint32_t*)&t2;
            *(uint4*)(fused + (size_t)(el + e) * 1024 + jc) = o;
            __syncwarp();
        }
    }
}

// ===== k_hdn: 4 warps, 64x64 warp tile; CHUNKED (reads L2-hot fused) ========
#define H_AS 0
#define H_BS 36864
#define H_TOTAL 71680

__global__ __launch_bounds__(128, 2) void k_hdn(
    const __nv_bfloat16* __restrict__ fused, const __nv_bfloat16* __restrict__ Wf1H,
    const float* __restrict__ bf1, const float* __restrict__ Wf2,
    float* __restrict__ logit, int ebase) {
    extern __shared__ char sm[];
    uint32_t smb = smem_u32(sm);
    __nv_bfloat16* As = (__nv_bfloat16*)(sm + H_AS);
    __nv_bfloat16* Bs = (__nv_bfloat16*)(sm + H_BS);

    int tid = threadIdx.x, w = tid >> 5, lane = tid & 31;
    int n0 = blockIdx.x * 128;
    int el = blockIdx.y * 128;
    int wm = w & 1, wn = w >> 1;

    auto stage = [&](int s) {
        int kc = s * 64, buf = s & 1;
#pragma unroll
        for (int i = tid; i < 1024; i += 128) {
            int r = i >> 3, c = (i & 7) * 8;
            cpa16(smb + H_AS + (uint32_t)((buf * 128 + r) * 72 + c) * 2,
                  fused + (size_t)(el + r) * 1024 + kc + c);
        }
#pragma unroll
        for (int i = tid; i < 1024; i += 128) {
            int r = i >> 4, c = (i & 15) * 8;
            cpa16(smb + H_BS + (uint32_t)((buf * 64 + r) * 136 + c) * 2,
                  Wf1H + (size_t)(kc + r) * 512 + n0 + c);
        }
    };

    FragC acc[4][4];
#pragma unroll
    for (int mt = 0; mt < 4; mt++)
#pragma unroll
        for (int nt = 0; nt < 4; nt++) wmma::fill_fragment(acc[mt][nt], 0.f);

    stage(0); CP_COMMIT();
    for (int s = 0; s < 16; s++) {
        if (s + 1 < 16) { stage(s + 1); CP_COMMIT(); CP_WAIT1(); }
        else { CP_WAIT0(); }
        __syncthreads();
        const __nv_bfloat16* Ab = As + (s & 1) * 128 * 72;
        const __nv_bfloat16* Bb = Bs + (s & 1) * 64 * 136;
#pragma unroll
        for (int k16 = 0; k16 < 4; k16++) {
            FragA a[4];
#pragma unroll
            for (int mt = 0; mt < 4; mt++)
                wmma::load_matrix_sync(a[mt], Ab + (wm * 64 + mt * 16) * 72 + k16 * 16, 72);
#pragma unroll
            for (int nt = 0; nt < 4; nt++) {
                FragB b;
                wmma::load_matrix_sync(b, Bb + (k16 * 16) * 136 + wn * 64 + nt * 16, 136);
#pragma unroll
                for (int mt = 0; mt < 4; mt++)
                    wmma::mma_sync(acc[mt][nt], a[mt], b, acc[mt][nt]);
            }
        }
        __syncthreads();
    }

    float* wscr = (float*)(sm + H_AS) + w * 256;
    int r = lane >> 1, cb = (lane & 1) * 8;
#pragma unroll
    for (int mt = 0; mt < 4; mt++) {
        float part = 0.f;
#pragma unroll
        for (int nt = 0; nt < 4; nt++) {
            wmma::store_matrix_sync(wscr, acc[mt][nt], 16, wmma::mem_row_major);
            __syncwarp();
            int ncol = n0 + wn * 64 + nt * 16 + cb;
            float4 v0 = *(float4*)(wscr + r * 16 + cb);
            float4 v1 = *(float4*)(wscr + r * 16 + cb + 4);
            float4 b0 = *(const float4*)(bf1 + ncol);
            float4 b1 = *(const float4*)(bf1 + ncol + 4);
            float4 w0 = *(const float4*)(Wf2 + ncol);
            float4 w1 = *(const float4*)(Wf2 + ncol + 4);
            part += fmaxf(v0.x + b0.x, 0.f) * w0.x + fmaxf(v0.y + b0.y, 0.f) * w0.y +
                    fmaxf(v0.z + b0.z, 0.f) * w0.z + fmaxf(v0.w + b0.w, 0.f) * w0.w +
                    fmaxf(v1.x + b1.x, 0.f) * w1.x + fmaxf(v1.y + b1.y, 0.f) * w1.y +
                    fmaxf(v1.z + b1.z, 0.f) * w1.z + fmaxf(v1.w + b1.w, 0.f) * w1.w;
            __syncwarp();
        }
        part += __shfl_xor_sync(0xffffffffu, part, 1);
        if ((lane & 1) == 0)
            atomicAdd(&logit[ebase + el + wm * 64 + mt * 16 + r], part);
    }
}

// ---------------- sigmoid ----------------
__global__ void k_sigmoid(const float* __restrict__ logit, const float* __restrict__ bf2,
                          float* __restrict__ outp) {
    int i = blockIdx.x * blockDim.x + threadIdx.x;
    if (i < EE) outp[i] = 1.f / (1.f + expf(-(logit[i] + bf2[0])));
}

// ---------------- launch ----------------
extern "C" void kernel_launch(void* const* d_in, const int* in_sizes, int n_in,
                              void* d_out, int out_size) {
    const float* x = (const float*)d_in[0];
    const int* ei = (const int*)d_in[1];
    const float* local_emb = (const float*)d_in[2];
    const float* W1 = (const float*)d_in[3];
    const float* a_src1 = (const float*)d_in[4];
    const float* a_trg1 = (const float*)d_in[5];
    const float* b1 = (const float*)d_in[6];
    const float* W2 = (const float*)d_in[7];
    const float* a_src2 = (const float*)d_in[8];
    const float* a_trg2 = (const float*)d_in[9];
    const float* b2 = (const float*)d_in[10];
    const float* Wi = (const float*)d_in[11];
    const float* bi = (const float*)d_in[12];
    const float* Wf1 = (const float*)d_in[13];
    const float* bf1 = (const float*)d_in[14];
    const float* Wf2 = (const float*)d_in[15];
    const float* bf2 = (const float*)d_in[16];
    float* outp = (float*)d_out;

    void* tmp;
    float *p_ssrc1, *p_strg1, *p_ssrc2, *p_strg2, *p_logit;
    __half *p_proj1h, *p_proj2h, *p_hh, *p_w2h;
    __nv_bfloat16 *p_out2h, *p_PQh, *p_wacad, *p_wibh, *p_wf1h, *p_msh, *p_fused;
#define SYM(p, s) cudaGetSymbolAddress(&tmp, s); p = (decltype(p))tmp;
    SYM(p_proj1h, g_proj1h) SYM(p_ssrc1, g_ssrc1) SYM(p_strg1, g_strg1)
    SYM(p_hh, g_hh) SYM(p_w2h, g_w2h)
    SYM(p_proj2h, g_proj2h) SYM(p_ssrc2, g_ssrc2) SYM(p_strg2, g_strg2)
    SYM(p_logit, g_logit)
    SYM(p_out2h, g_out2h) SYM(p_PQh, g_PQh) SYM(p_wacad, g_wacad)
    SYM(p_wibh, g_wib_h) SYM(p_wf1h, g_wf1_h) SYM(p_msh, g_msh) SYM(p_fused, g_fused)
#undef SYM

    cudaFuncSetAttribute(k_gemm_tf32h<128, 256>,
                         cudaFuncAttributeMaxDynamicSharedMemorySize, TF32_SMEM);
    cudaFuncSetAttribute(k_fused, cudaFuncAttributeMaxDynamicSharedMemorySize, F_TOTAL);
    cudaFuncSetAttribute(k_hdn, cudaFuncAttributeMaxDynamicSharedMemorySize, H_TOTAL);

    const int EB = (EE + 255) / 256;

    k_init<<<256, 256>>>();
    k_wprep<<<1024, 256>>>(Wi, p_wacad, p_wibh);
    k_cvt_wf1<<<2048, 256>>>(Wf1, p_wf1h);
    k_cvt_w2<<<1024, 256>>>(W2, p_w2h);

    // ---- edge sort by target ----
    k_hist<<<EB, 256>>>(ei);
    k_scan<<<1, 1024>>>();
    k_sortE<<<EB, 256>>>(ei);

    // ---- GAT layer 1 ----
    k_gemm_tf32h<128, 256><<<dim3(NP / 128, 2), 256, TF32_SMEM>>>(x, W1, p_proj1h);
    k_scores<2><<<NN, 64>>>(p_proj1h, a_src1, a_trg1, p_ssrc1, p_strg1);
    k_agg1<<<(NN + 7) / 8, 256>>>(p_ssrc1, p_strg1, p_proj1h, local_emb, b1, p_hh);

    // ---- GAT layer 2 (fp16 HMMA) ----
    k_gemm_fp16<512, 512><<<dim3(NP / 128, 4), 256>>>(p_hh, p_w2h, p_proj2h);
    k_scores<4><<<NN, 128>>>(p_proj2h, a_src2, a_trg2, p_ssrc2, p_strg2);
    k_agg2<<<(NN + 7) / 8, 256>>>(p_ssrc2, p_strg2, p_proj2h, b2, p_out2h);

    // ---- P|Q combined bf16 GEMM ----
    k_gemm_bf16h<128, 2048><<<dim3(NP / 128, 16), 256>>>(p_out2h, p_wacad, p_PQh);

    // ---- edge MLP: chunked so the fused intermediate stays L2-resident ----
    k_msh<<<EE / 8, 256>>>(ei, p_out2h, p_msh);
    for (int ch = 0; ch < EE / ECHUNK; ch++) {
        int ebase = ch * ECHUNK;
        k_fused<<<dim3(8, ECHUNK / 128), 128, F_TOTAL>>>(ei, p_msh, p_wibh, p_PQh, bi,
                                                         p_fused, ebase);
        k_hdn<<<dim3(4, ECHUNK / 128), 128, H_TOTAL>>>(p_fused, p_wf1h, bf1, Wf2,
                                                       p_logit, ebase);
    }
    k_sigmoid<<<EB, 256>>>(p_logit, bf2, outp);
}

// round 17
// speedup vs baseline: 1.1653x; 1.1653x over previous
#include <cuda_runtime.h>
#include <cuda_bf16.h>
#include <cuda_fp16.h>
#include <mma.h>
#include <math.h>
#include <cstdint>

using namespace nvcuda;

#define NN 10000
#define NP 10112
#define EE 160000

// ---------------- device scratch ----------------
__device__ __half g_proj1h[NP * 256];
__device__ float g_ssrc1[NN * 2];
__device__ float g_strg1[NN * 2];
__device__ __half g_hh[NP * 512];
__device__ __half g_w2h[512 * 512];
__device__ __half g_proj2h[NP * 512];
__device__ float g_ssrc2[NN * 4];
__device__ float g_strg2[NN * 4];
__device__ __nv_bfloat16 g_out2h[NP * 128];
__device__ __nv_bfloat16 g_PQh[NP * 2048];
__device__ __nv_bfloat16 g_wacad[128 * 2048];
__device__ __nv_bfloat16 g_wib_h[128 * 1024];
__device__ __nv_bfloat16 g_wf1_h[1024 * 512];
__device__ __nv_bfloat16 g_msh[EE * 128];
__device__ __nv_bfloat16 g_fused[(size_t)EE * 1024];
__device__ float g_logit[EE];
// edge sort (by target)
__device__ int g_deg[NN];
__device__ int g_off[NN + 1];
__device__ int g_cur[NN];
__device__ int g_srt[EE];

__device__ __forceinline__ float eluf(float v) { return v > 0.f ? v : expm1f(v); }

__device__ __forceinline__ uint32_t smem_u32(const void* p) {
    uint32_t a;
    asm("{ .reg .u64 t; cvta.to.shared.u64 t, %1; cvt.u32.u64 %0, t; }" : "=r"(a) : "l"(p));
    return a;
}
__device__ __forceinline__ void cpa16(uint32_t saddr, const void* g) {
    asm volatile("cp.async.cg.shared.global [%0], [%1], 16;" :: "r"(saddr), "l"(g));
}
__device__ __forceinline__ void cpa16p(uint32_t saddr, const void* g, bool pred) {
    int sz = pred ? 16 : 0;
    asm volatile("cp.async.cg.shared.global [%0], [%1], 16, %2;"
                 :: "r"(saddr), "l"(g), "r"(sz));
}
#define CP_COMMIT() asm volatile("cp.async.commit_group;" ::: "memory")
#define CP_WAIT0()  asm volatile("cp.async.wait_group 0;" ::: "memory")
#define CP_WAIT1()  asm volatile("cp.async.wait_group 1;" ::: "memory")

// ---------------- init ----------------
__global__ void k_init() {
    int i = blockIdx.x * blockDim.x + threadIdx.x;
    int stride = gridDim.x * blockDim.x;
    for (int j = i; j < EE; j += stride) g_logit[j] = 0.f;
    for (int j = i; j < NN; j += stride) g_deg[j] = 0;
}

// ---------------- edge sort by target ----------------
__global__ void k_hist(const int* __restrict__ ei) {
    int i = blockIdx.x * blockDim.x + threadIdx.x;
    if (i < EE) atomicAdd(&g_deg[ei[EE + i]], 1);
}

__global__ void k_scan() {
    __shared__ int ps[1024];
    int tid = threadIdx.x;
    int base = tid * 10;
    int local[10];
    int s = 0;
#pragma unroll
    for (int k = 0; k < 10; k++) {
        int idx = base + k;
        local[k] = s;
        if (idx < NN) s += g_deg[idx];
    }
    ps[tid] = s;
    __syncthreads();
    for (int o = 1; o < 1024; o <<= 1) {
        int v = (tid >= o) ? ps[tid - o] : 0;
        __syncthreads();
        ps[tid] += v;
        __syncthreads();
    }
    int pre = (tid == 0) ? 0 : ps[tid - 1];
#pragma unroll
    for (int k = 0; k < 10; k++) {
        int idx = base + k;
        if (idx < NN) { g_off[idx] = pre + local[k]; g_cur[idx] = pre + local[k]; }
    }
    if (tid == 1023) g_off[NN] = ps[1023];
}

__global__ void k_sortE(const int* __restrict__ ei) {
    int i = blockIdx.x * blockDim.x + threadIdx.x;
    if (i >= EE) return;
    int t = ei[EE + i];
    int p = atomicAdd(&g_cur[t], 1);
    g_srt[p] = ei[i];
}

// ====== tf32 GEMM, fp16 output — layer-1 projection =========================
template <int K, int COLS>
__global__ __launch_bounds__(256) void k_gemm_tf32h(const float* __restrict__ A,
                                                    const float* __restrict__ W,
                                                    __half* __restrict__ C) {
    constexpr int KC = 32;
    constexpr int NSTG = K / KC;
    extern __shared__ float smf[];
    float* As = smf;
    float* Ws = smf + 2 * 128 * 36;
    uint32_t asb = smem_u32(As), wsb = smem_u32(Ws);
    int m0 = blockIdx.x * 128, n0 = blockIdx.y * 128;
    int tid = threadIdx.x, w = tid >> 5, lane = tid & 31;
    int wm = w & 1, wn = w >> 1;

    auto stage = [&](int s) {
        int kc = s * KC, buf = s & 1;
#pragma unroll
        for (int i = tid; i < 1024; i += 256) {
            int r = i >> 3, c = (i & 7) * 4;
            int gm = m0 + r;
            const float* src = (gm < NN) ? (A + (size_t)gm * K + kc + c) : A;
            cpa16p(asb + (uint32_t)((buf * 128 + r) * 36 + c) * 4, src, gm < NN);
        }
#pragma unroll
        for (int i = tid; i < 1024; i += 256) {
            int r = i >> 5, c = (i & 31) * 4;
            cpa16(wsb + (uint32_t)((buf * 32 + r) * 132 + c) * 4,
                  W + (size_t)(kc + r) * COLS + n0 + c);
        }
    };

    wmma::fragment<wmma::accumulator, 16, 16, 8, float> acc[4][2];
#pragma unroll
    for (int mt = 0; mt < 4; mt++)
#pragma unroll
        for (int nt = 0; nt < 2; nt++) wmma::fill_fragment(acc[mt][nt], 0.f);

    stage(0); CP_COMMIT();
    for (int s = 0; s < NSTG; s++) {
        if (s + 1 < NSTG) { stage(s + 1); CP_COMMIT(); CP_WAIT1(); }
        else { CP_WAIT0(); }
        __syncthreads();
        const float* Ab = As + (s & 1) * 128 * 36;
        const float* Wb = Ws + (s & 1) * 32 * 132;
#pragma unroll
        for (int k8 = 0; k8 < KC / 8; k8++) {
            wmma::fragment<wmma::matrix_a, 16, 16, 8, wmma::precision::tf32,
                           wmma::row_major> a[4];
#pragma unroll
            for (int mt = 0; mt < 4; mt++)
                wmma::load_matrix_sync(a[mt], Ab + (wm * 64 + mt * 16) * 36 + k8 * 8, 36);
#pragma unroll
            for (int nt = 0; nt < 2; nt++) {
                wmma::fragment<wmma::matrix_b, 16, 16, 8, wmma::precision::tf32,
                               wmma::row_major> b;
                wmma::load_matrix_sync(b, Wb + (k8 * 8) * 132 + wn * 32 + nt * 16, 132);
#pragma unroll
                for (int mt = 0; mt < 4; mt++)
                    wmma::mma_sync(acc[mt][nt], a[mt], b, acc[mt][nt]);
            }
        }
        __syncthreads();
    }
    float* scratch = As + w * 256;
#pragma unroll
    for (int mt = 0; mt < 4; mt++)
#pragma unroll
        for (int nt = 0; nt < 2; nt++) {
            wmma::store_matrix_sync(scratch, acc[mt][nt], 16, wmma::mem_row_major);
            __syncwarp();
            int row = lane >> 1, colb = (lane & 1) * 8;
            const float* sp = scratch + row * 16 + colb;
            int gm = m0 + wm * 64 + mt * 16 + row;
            __half* dst = C + (size_t)gm * COLS + n0 + wn * 32 + nt * 16 + colb;
            uint4 o;
            __half2 t;
            t = __floats2half2_rn(sp[0], sp[1]); o.x = *(uint32_t*)&t;
            t = __floats2half2_rn(sp[2], sp[3]); o.y = *(uint32_t*)&t;
            t = __floats2half2_rn(sp[4], sp[5]); o.z = *(uint32_t*)&t;
            t = __floats2half2_rn(sp[6], sp[7]); o.w = *(uint32_t*)&t;
            *(uint4*)dst = o;
            __syncwarp();
        }
}
#define TF32_SMEM ((2 * 128 * 36 + 2 * 32 * 132) * 4)

// ====== fp16 GEMM — layer-2 projection ======================================
template <int K, int COLS>
__global__ __launch_bounds__(256) void k_gemm_fp16(const __half* __restrict__ A,
                                                   const __half* __restrict__ W,
                                                   __half* __restrict__ C) {
    constexpr int KC = 32;
    constexpr int NSTG = K / KC;
    __shared__ __half As[2][128][40];
    __shared__ __half Ws[2][KC][136];
    uint32_t asb = smem_u32(&As[0][0][0]), wsb = smem_u32(&Ws[0][0][0]);
    int m0 = blockIdx.x * 128, n0 = blockIdx.y * 128;
    int tid = threadIdx.x, w = tid >> 5, lane = tid & 31;
    int wm = w & 1, wn = w >> 1;

    auto stage = [&](int s) {
        int kc = s * KC, buf = s & 1;
#pragma unroll
        for (int i = tid; i < 512; i += 256) {
            int r = i >> 2, c = (i & 3) * 8;
            cpa16(asb + (uint32_t)((buf * 128 + r) * 40 + c) * 2,
                  A + (size_t)(m0 + r) * K + kc + c);
        }
#pragma unroll
        for (int i = tid; i < 512; i += 256) {
            int r = i >> 4, c = (i & 15) * 8;
            cpa16(wsb + (uint32_t)((buf * KC + r) * 136 + c) * 2,
                  W + (size_t)(kc + r) * COLS + n0 + c);
        }
    };

    wmma::fragment<wmma::accumulator, 16, 16, 16, float> acc[4][2];
#pragma unroll
    for (int mt = 0; mt < 4; mt++)
#pragma unroll
        for (int nt = 0; nt < 2; nt++) wmma::fill_fragment(acc[mt][nt], 0.f);

    stage(0); CP_COMMIT();
    for (int s = 0; s < NSTG; s++) {
        if (s + 1 < NSTG) { stage(s + 1); CP_COMMIT(); CP_WAIT1(); }
        else { CP_WAIT0(); }
        __syncthreads();
        const __half* Ab = &As[s & 1][0][0];
        const __half* Wb = &Ws[s & 1][0][0];
#pragma unroll
        for (int k16 = 0; k16 < KC / 16; k16++) {
            wmma::fragment<wmma::matrix_a, 16, 16, 16, __half, wmma::row_major> a[4];
#pragma unroll
            for (int mt = 0; mt < 4; mt++)
                wmma::load_matrix_sync(a[mt], Ab + (wm * 64 + mt * 16) * 40 + k16 * 16, 40);
#pragma unroll
            for (int nt = 0; nt < 2; nt++) {
                wmma::fragment<wmma::matrix_b, 16, 16, 16, __half, wmma::row_major> b;
                wmma::load_matrix_sync(b, Wb + (k16 * 16) * 136 + wn * 32 + nt * 16, 136);
#pragma unroll
                for (int mt = 0; mt < 4; mt++)
                    wmma::mma_sync(acc[mt][nt], a[mt], b, acc[mt][nt]);
            }
        }
        __syncthreads();
    }
    float* scratch = (float*)(&As[0][0][0]) + w * 256;
#pragma unroll
    for (int mt = 0; mt < 4; mt++)
#pragma unroll
        for (int nt = 0; nt < 2; nt++) {
            wmma::store_matrix_sync(scratch, acc[mt][nt], 16, wmma::mem_row_major);
            __syncwarp();
            int row = lane >> 1, colb = (lane & 1) * 8;
            const float* sp = scratch + row * 16 + colb;
            int gm = m0 + wm * 64 + mt * 16 + row;
            __half* dst = C + (size_t)gm * COLS + n0 + wn * 32 + nt * 16 + colb;
            uint4 o;
            __half2 t;
            t = __floats2half2_rn(sp[0], sp[1]); o.x = *(uint32_t*)&t;
            t = __floats2half2_rn(sp[2], sp[3]); o.y = *(uint32_t*)&t;
            t = __floats2half2_rn(sp[4], sp[5]); o.z = *(uint32_t*)&t;
            t = __floats2half2_rn(sp[6], sp[7]); o.w = *(uint32_t*)&t;
            *(uint4*)dst = o;
            __syncwarp();
        }
}

// ====== bf16 GEMM — for P|Q =================================================
template <int K, int COLS>
__global__ __launch_bounds__(256) void k_gemm_bf16h(const __nv_bfloat16* __restrict__ A,
                                                    const __nv_bfloat16* __restrict__ W,
                                                    __nv_bfloat16* __restrict__ C) {
    constexpr int KC = 32;
    constexpr int NSTG = K / KC;
    __shared__ __nv_bfloat16 As[2][128][40];
    __shared__ __nv_bfloat16 Ws[2][KC][136];
    uint32_t asb = smem_u32(&As[0][0][0]), wsb = smem_u32(&Ws[0][0][0]);
    int m0 = blockIdx.x * 128, n0 = blockIdx.y * 128;
    int tid = threadIdx.x, w = tid >> 5, lane = tid & 31;
    int wm = w & 1, wn = w >> 1;

    auto stage = [&](int s) {
        int kc = s * KC, buf = s & 1;
#pragma unroll
        for (int i = tid; i < 512; i += 256) {
            int r = i >> 2, c = (i & 3) * 8;
            cpa16(asb + (uint32_t)((buf * 128 + r) * 40 + c) * 2,
                  A + (size_t)(m0 + r) * K + kc + c);
        }
#pragma unroll
        for (int i = tid; i < 512; i += 256) {
            int r = i >> 4, c = (i & 15) * 8;
            cpa16(wsb + (uint32_t)((buf * KC + r) * 136 + c) * 2,
                  W + (size_t)(kc + r) * COLS + n0 + c);
        }
    };

    wmma::fragment<wmma::accumulator, 16, 16, 16, float> acc[4][2];
#pragma unroll
    for (int mt = 0; mt < 4; mt++)
#pragma unroll
        for (int nt = 0; nt < 2; nt++) wmma::fill_fragment(acc[mt][nt], 0.f);

    stage(0); CP_COMMIT();
    for (int s = 0; s < NSTG; s++) {
        if (s + 1 < NSTG) { stage(s + 1); CP_COMMIT(); CP_WAIT1(); }
        else { CP_WAIT0(); }
        __syncthreads();
        const __nv_bfloat16* Ab = &As[s & 1][0][0];
        const __nv_bfloat16* Wb = &Ws[s & 1][0][0];
#pragma unroll
        for (int k16 = 0; k16 < KC / 16; k16++) {
            wmma::fragment<wmma::matrix_a, 16, 16, 16, __nv_bfloat16, wmma::row_major> a[4];
#pragma unroll
            for (int mt = 0; mt < 4; mt++)
                wmma::load_matrix_sync(a[mt], Ab + (wm * 64 + mt * 16) * 40 + k16 * 16, 40);
#pragma unroll
            for (int nt = 0; nt < 2; nt++) {
                wmma::fragment<wmma::matrix_b, 16, 16, 16, __nv_bfloat16, wmma::row_major> b;
                wmma::load_matrix_sync(b, Wb + (k16 * 16) * 136 + wn * 32 + nt * 16, 136);
#pragma unroll
                for (int mt = 0; mt < 4; mt++)
                    wmma::mma_sync(acc[mt][nt], a[mt], b, acc[mt][nt]);
            }
        }
        __syncthreads();
    }
    float* scratch = (float*)(&As[0][0][0]) + w * 256;
#pragma unroll
    for (int mt = 0; mt < 4; mt++)
#pragma unroll
        for (int nt = 0; nt < 2; nt++) {
            wmma::store_matrix_sync(scratch, acc[mt][nt], 16, wmma::mem_row_major);
            __syncwarp();
            int row = lane >> 1, colb = (lane & 1) * 8;
            const float* sp = scratch + row * 16 + colb;
            int gm = m0 + wm * 64 + mt * 16 + row;
            __nv_bfloat16* dst = C + (size_t)gm * COLS + n0 + wn * 32 + nt * 16 + colb;
            uint4 o;
            __nv_bfloat162 t;
            t = __floats2bfloat162_rn(sp[0], sp[1]); o.x = *(uint32_t*)&t;
            t = __floats2bfloat162_rn(sp[2], sp[3]); o.y = *(uint32_t*)&t;
            t = __floats2bfloat162_rn(sp[4], sp[5]); o.z = *(uint32_t*)&t;
            t = __floats2bfloat162_rn(sp[6], sp[7]); o.w = *(uint32_t*)&t;
            *(uint4*)dst = o;
            __syncwarp();
        }
}

// ---------------- attention score projections (fp16 proj) ----------------
template <int H>
__global__ void k_scores(const __half* __restrict__ proj, const float* __restrict__ asrc,
                         const float* __restrict__ atrg, float* __restrict__ ssrc,
                         float* __restrict__ strg) {
    int n = blockIdx.x;
    int h = threadIdx.x >> 5, lane = threadIdx.x & 31;
    uint2 pu = *(const uint2*)(proj + ((size_t)n * H + h) * 128 + lane * 4);
    float2 p01 = __half22float2(*(__half2*)&pu.x);
    float2 p23 = __half22float2(*(__half2*)&pu.y);
    float4 a = *(const float4*)(asrc + h * 128 + lane * 4);
    float4 b = *(const float4*)(atrg + h * 128 + lane * 4);
    float ps = p01.x * a.x + p01.y * a.y + p23.x * a.z + p23.y * a.w;
    float pt = p01.x * b.x + p01.y * b.y + p23.x * b.z + p23.y * b.w;
#pragma unroll
    for (int o = 16; o > 0; o >>= 1) {
        ps += __shfl_down_sync(0xffffffffu, ps, o);
        pt += __shfl_down_sync(0xffffffffu, pt, o);
    }
    if (lane == 0) { ssrc[n * H + h] = ps; strg[n * H + h] = pt; }
}

// ===== gather-side agg layer 1 (H=2) + finalize1, software-pipelined ========
__global__ __launch_bounds__(256) void k_agg1(
    const float* __restrict__ ss, const float* __restrict__ st,
    const __half* __restrict__ proj, const float* __restrict__ local_emb,
    const float* __restrict__ b1, __half* __restrict__ hbuf) {
    int t = blockIdx.x * 8 + (threadIdx.x >> 5);
    int lane = threadIdx.x & 31;
    if (t >= NN) return;
    float st0 = st[t * 2], st1 = st[t * 2 + 1];
    float a0[4] = {0.f, 0.f, 0.f, 0.f}, a1[4] = {0.f, 0.f, 0.f, 0.f};
    float d0 = 0.f, d1 = 0.f;
    int jb = g_off[t], je = g_off[t + 1];
    // software pipeline: prefetch src index + its scores one iteration ahead
    int sN = 0;
    float sN0 = 0.f, sN1 = 0.f;
    if (jb < je) {
        sN = __ldg(&g_srt[jb]);
        sN0 = __ldg(&ss[sN * 2]);
        sN1 = __ldg(&ss[sN * 2 + 1]);
    }
    for (int j = jb; j < je; j++) {
        int s = sN;
        float v0 = sN0 + st0, v1 = sN1 + st1;
        // issue proj loads immediately (address ready from prefetch)
        uint2 p0 = *(const uint2*)(proj + (size_t)s * 256 + lane * 4);
        uint2 p1 = *(const uint2*)(proj + (size_t)s * 256 + 128 + lane * 4);
        if (j + 1 < je) {
            sN = __ldg(&g_srt[j + 1]);
            sN0 = __ldg(&ss[sN * 2]);
            sN1 = __ldg(&ss[sN * 2 + 1]);
        }
        v0 = v0 > 0.f ? v0 : 0.2f * v0;
        v1 = v1 > 0.f ? v1 : 0.2f * v1;
        float e0 = expf(v0), e1 = expf(v1);
        d0 += e0; d1 += e1;
        float2 x01 = __half22float2(*(__half2*)&p0.x);
        float2 x23 = __half22float2(*(__half2*)&p0.y);
        a0[0] += e0 * x01.x; a0[1] += e0 * x01.y;
        a0[2] += e0 * x23.x; a0[3] += e0 * x23.y;
        float2 y01 = __half22float2(*(__half2*)&p1.x);
        float2 y23 = __half22float2(*(__half2*)&p1.y);
        a1[0] += e1 * y01.x; a1[1] += e1 * y01.y;
        a1[2] += e1 * y23.x; a1[3] += e1 * y23.y;
    }
    float i0 = 1.f / (d0 + 1e-16f), i1 = 1.f / (d1 + 1e-16f);
    int c = lane * 4;
    float4 le = *(const float4*)(local_emb + (size_t)t * 128 + c);
    {
        float4 bv = *(const float4*)(b1 + c);
        __half2 o0 = __floats2half2_rn(eluf(a0[0] * i0 + bv.x), eluf(a0[1] * i0 + bv.y));
        __half2 o1 = __floats2half2_rn(eluf(a0[2] * i0 + bv.z), eluf(a0[3] * i0 + bv.w));
        uint2 o = {*(uint32_t*)&o0, *(uint32_t*)&o1};
        *(uint2*)(hbuf + (size_t)t * 512 + c) = o;
        float4 bl = *(const float4*)(b1 + 128 + c);
        o0 = __floats2half2_rn(eluf(le.x + bl.x), eluf(le.y + bl.y));
        o1 = __floats2half2_rn(eluf(le.z + bl.z), eluf(le.w + bl.w));
        uint2 ol = {*(uint32_t*)&o0, *(uint32_t*)&o1};
        *(uint2*)(hbuf + (size_t)t * 512 + 128 + c) = ol;
    }
    {
        float4 bv = *(const float4*)(b1 + 256 + c);
        __half2 o0 = __floats2half2_rn(eluf(a1[0] * i1 + bv.x), eluf(a1[1] * i1 + bv.y));
        __half2 o1 = __floats2half2_rn(eluf(a1[2] * i1 + bv.z), eluf(a1[3] * i1 + bv.w));
        uint2 o = {*(uint32_t*)&o0, *(uint32_t*)&o1};
        *(uint2*)(hbuf + (size_t)t * 512 + 256 + c) = o;
        float4 bl = *(const float4*)(b1 + 384 + c);
        o0 = __floats2half2_rn(eluf(le.x + bl.x), eluf(le.y + bl.y));
        o1 = __floats2half2_rn(eluf(le.z + bl.z), eluf(le.w + bl.w));
        uint2 ol = {*(uint32_t*)&o0, *(uint32_t*)&o1};
        *(uint2*)(hbuf + (size_t)t * 512 + 384 + c) = ol;
    }
}

// ===== gather-side agg layer 2 (H=4, mean) + finalize2, software-pipelined ==
__global__ __launch_bounds__(256) void k_agg2(
    const float* __restrict__ ss, const float* __restrict__ st,
    const __half* __restrict__ proj, const float* __restrict__ b2,
    __nv_bfloat16* __restrict__ out2h) {
    int t = blockIdx.x * 8 + (threadIdx.x >> 5);
    int lane = threadIdx.x & 31;
    if (t >= NN) return;
    float sth[4];
#pragma unroll
    for (int h = 0; h < 4; h++) sth[h] = st[t * 4 + h];
    float acc[4][4];
#pragma unroll
    for (int h = 0; h < 4; h++)
#pragma unroll
        for (int k = 0; k < 4; k++) acc[h][k] = 0.f;
    float den[4] = {0.f, 0.f, 0.f, 0.f};
    int jb = g_off[t], je = g_off[t + 1];
    int sN = 0;
    float4 scN = make_float4(0.f, 0.f, 0.f, 0.f);
    if (jb < je) {
        sN = __ldg(&g_srt[jb]);
        scN = *(const float4*)(ss + sN * 4);
    }
    for (int j = jb; j < je; j++) {
        int s = sN;
        float4 sc = scN;
        // issue all 4 proj loads immediately (addresses ready)
        uint2 pu0 = *(const uint2*)(proj + (size_t)s * 512 + 0 * 128 + lane * 4);
        uint2 pu1 = *(const uint2*)(proj + (size_t)s * 512 + 1 * 128 + lane * 4);
        uint2 pu2 = *(const uint2*)(proj + (size_t)s * 512 + 2 * 128 + lane * 4);
        uint2 pu3 = *(const uint2*)(proj + (size_t)s * 512 + 3 * 128 + lane * 4);
        if (j + 1 < je) {
            sN = __ldg(&g_srt[j + 1]);
            scN = *(const float4*)(ss + sN * 4);
        }
        float v0 = sc.x + sth[0], v1 = sc.y + sth[1];
        float v2 = sc.z + sth[2], v3 = sc.w + sth[3];
        v0 = v0 > 0.f ? v0 : 0.2f * v0;
        v1 = v1 > 0.f ? v1 : 0.2f * v1;
        v2 = v2 > 0.f ? v2 : 0.2f * v2;
        v3 = v3 > 0.f ? v3 : 0.2f * v3;
        float e0 = expf(v0), e1 = expf(v1), e2 = expf(v2), e3 = expf(v3);
        den[0] += e0; den[1] += e1; den[2] += e2; den[3] += e3;
        float2 x, y;
        x = __half22float2(*(__half2*)&pu0.x); y = __half22float2(*(__half2*)&pu0.y);
        acc[0][0] += e0 * x.x; acc[0][1] += e0 * x.y;
        acc[0][2] += e0 * y.x; acc[0][3] += e0 * y.y;
        x = __half22float2(*(__half2*)&pu1.x); y = __half22float2(*(__half2*)&pu1.y);
        acc[1][0] += e1 * x.x; acc[1][1] += e1 * x.y;
        acc[1][2] += e1 * y.x; acc[1][3] += e1 * y.y;
        x = __half22float2(*(__half2*)&pu2.x); y = __half22float2(*(__half2*)&pu2.y);
        acc[2][0] += e2 * x.x; acc[2][1] += e2 * x.y;
        acc[2][2] += e2 * y.x; acc[2][3] += e2 * y.y;
        x = __half22float2(*(__half2*)&pu3.x); y = __half22float2(*(__half2*)&pu3.y);
        acc[3][0] += e3 * x.x; acc[3][1] += e3 * x.y;
        acc[3][2] += e3 * y.x; acc[3][3] += e3 * y.y;
    }
    float inv[4];
#pragma unroll
    for (int h = 0; h < 4; h++) inv[h] = 1.f / (den[h] + 1e-16f);
    int f = lane * 4;
    float4 bv = *(const float4*)(b2 + f);
    float r[4];
#pragma unroll
    for (int k = 0; k < 4; k++) {
        float v = acc[0][k] * inv[0] + acc[1][k] * inv[1] +
                  acc[2][k] * inv[2] + acc[3][k] * inv[3];
        float bb = (k == 0) ? bv.x : (k == 1) ? bv.y : (k == 2) ? bv.z : bv.w;
        r[k] = eluf(0.25f * v + bb);
    }
    __nv_bfloat162 o0 = __floats2bfloat162_rn(r[0], r[1]);
    __nv_bfloat162 o1 = __floats2bfloat162_rn(r[2], r[3]);
    uint2 o = {*(uint32_t*)&o0, *(uint32_t*)&o1};
    *(uint2*)(out2h + (size_t)t * 128 + f) = o;
}

// ---------------- MLP weight prep ----------------
__global__ void k_wprep(const float* __restrict__ Wi, __nv_bfloat16* __restrict__ wacad,
                        __nv_bfloat16* __restrict__ wibh) {
    int i = blockIdx.x * blockDim.x + threadIdx.x;
    if (i >= 128 * 2048) return;
    int k = i >> 11, j = i & 2047;
    float v;
    if (j < 1024)
        v = Wi[(size_t)k * 1024 + j] + Wi[(size_t)(256 + k) * 1024 + j];
    else
        v = Wi[(size_t)k * 1024 + (j - 1024)] + Wi[(size_t)(384 + k) * 1024 + (j - 1024)];
    wacad[i] = __float2bfloat16(v);
    if (j < 1024) wibh[(size_t)k * 1024 + j] = __float2bfloat16(Wi[(size_t)(128 + k) * 1024 + j]);
}

__global__ void k_cvt_wf1(const float* __restrict__ Wf1, __nv_bfloat16* __restrict__ out) {
    int i = blockIdx.x * blockDim.x + threadIdx.x;
    if (i < 1024 * 512) out[i] = __float2bfloat16(Wf1[i]);
}

__global__ void k_cvt_w2(const float* __restrict__ W2, __half* __restrict__ out) {
    int i = blockIdx.x * blockDim.x + threadIdx.x;
    if (i < 512 * 512) out[i] = __float2half(W2[i]);
}

// ---------------- msh = bf16(e1 * e2) ----------------
__global__ void k_msh(const int* __restrict__ ei, const __nv_bfloat16* __restrict__ out2h,
                      __nv_bfloat16* __restrict__ msh) {
    int g = blockIdx.x * blockDim.x + threadIdx.x;
    int e = g >> 5, lane = g & 31;
    if (e >= EE) return;
    int s = ei[e], t = ei[EE + e];
    uint2 au = *(const uint2*)(out2h + (size_t)s * 128 + lane * 4);
    uint2 bu = *(const uint2*)(out2h + (size_t)t * 128 + lane * 4);
    uint2 o;
    *(__nv_bfloat162*)&o.x = __hmul2(*(__nv_bfloat162*)&au.x, *(__nv_bfloat162*)&bu.x);
    *(__nv_bfloat162*)&o.y = __hmul2(*(__nv_bfloat162*)&au.y, *(__nv_bfloat162*)&bu.y);
    *(uint2*)(msh + (size_t)e * 128 + lane * 4) = o;
}

// ===== k_fused: 4 warps, warp tile 64x64 ====================================
#define F_AS 0
#define F_BS 34816
#define F_SCR 69632
#define F_SIDX 73728
#define F_TIDX 74240
#define F_TOTAL 74752

typedef wmma::fragment<wmma::matrix_a, 16, 16, 16, __nv_bfloat16, wmma::row_major> FragA;
typedef wmma::fragment<wmma::matrix_b, 16, 16, 16, __nv_bfloat16, wmma::row_major> FragB;
typedef wmma::fragment<wmma::accumulator, 16, 16, 16, float> FragC;

__global__ __launch_bounds__(128, 2) void k_fused(
    const int* __restrict__ ei, const __nv_bfloat16* __restrict__ msh,
    const __nv_bfloat16* __restrict__ WibH, const __nv_bfloat16* __restrict__ PQh,
    const float* __restrict__ bi, __nv_bfloat16* __restrict__ fused) {
    extern __shared__ char sm[];
    __nv_bfloat16* As = (__nv_bfloat16*)(sm + F_AS);
    __nv_bfloat16* Bs = (__nv_bfloat16*)(sm + F_BS);
    float* scr = (float*)(sm + F_SCR);
    int* sidx = (int*)(sm + F_SIDX);
    int* tidx = (int*)(sm + F_TIDX);
    uint32_t smb = smem_u32(sm);

    int tid = threadIdx.x, w = tid >> 5, lane = tid & 31;
    int n0 = blockIdx.x * 128, e0 = blockIdx.y * 128;
    int wm = w & 1, wn = w >> 1;

    sidx[tid] = ei[e0 + tid];
    tidx[tid] = ei[EE + e0 + tid];

#pragma unroll
    for (int i = tid; i < 2048; i += 128) {
        int r = i >> 4, c = (i & 15) * 8;
        cpa16(smb + F_AS + (uint32_t)(r * 136 + c) * 2, msh + (size_t)(e0 + r) * 128 + c);
    }
#pragma unroll
    for (int i = tid; i < 2048; i += 128) {
        int r = i >> 4, c = (i & 15) * 8;
        cpa16(smb + F_BS + (uint32_t)(r * 136 + c) * 2, WibH + (size_t)r * 1024 + n0 + c);
    }
    CP_COMMIT(); CP_WAIT0();
    __syncthreads();

    FragC acc[4][4];
#pragma unroll
    for (int mt = 0; mt < 4; mt++)
#pragma unroll
        for (int nt = 0; nt < 4; nt++) wmma::fill_fragment(acc[mt][nt], 0.f);
#pragma unroll
    for (int k16 = 0; k16 < 8; k16++) {
        FragA a[4];
#pragma unroll
        for (int mt = 0; mt < 4; mt++)
            wmma::load_matrix_sync(a[mt], As + (wm * 64 + mt * 16) * 136 + k16 * 16, 136);
#pragma unroll
        for (int nt = 0; nt < 4; nt++) {
            FragB b;
            wmma::load_matrix_sync(b, Bs + (k16 * 16) * 136 + wn * 64 + nt * 16, 136);
#pragma unroll
            for (int mt = 0; mt < 4; mt++)
                wmma::mma_sync(acc[mt][nt], a[mt], b, acc[mt][nt]);
        }
    }

    float* wscr = scr + w * 256;
    int r = lane >> 1, cb = (lane & 1) * 8;
#pragma unroll
    for (int mt = 0; mt < 4; mt++) {
#pragma unroll
        for (int nt = 0; nt < 4; nt++) {
            wmma::store_matrix_sync(wscr, acc[mt][nt], 16, wmma::mem_row_major);
            __syncwarp();
            int e = wm * 64 + mt * 16 + r;
            int jc = n0 + wn * 64 + nt * 16 + cb;
            float4 v0 = *(float4*)(wscr + r * 16 + cb);
            float4 v1 = *(float4*)(wscr + r * 16 + cb + 4);
            uint4 pu = *(const uint4*)(PQh + (size_t)sidx[e] * 2048 + jc);
            uint4 qu = *(const uint4*)(PQh + (size_t)tidx[e] * 2048 + 1024 + jc);
            float4 bi0 = *(const float4*)(bi + jc);
            float4 bi1 = *(const float4*)(bi + jc + 4);
            float2 p01 = __bfloat1622float2(*(__nv_bfloat162*)&pu.x);
            float2 p23 = __bfloat1622float2(*(__nv_bfloat162*)&pu.y);
            float2 p45 = __bfloat1622float2(*(__nv_bfloat162*)&pu.z);
            float2 p67 = __bfloat1622float2(*(__nv_bfloat162*)&pu.w);
            float2 q01 = __bfloat1622float2(*(__nv_bfloat162*)&qu.x);
            float2 q23 = __bfloat1622float2(*(__nv_bfloat162*)&qu.y);
            float2 q45 = __bfloat1622float2(*(__nv_bfloat162*)&qu.z);
            float2 q67 = __bfloat1622float2(*(__nv_bfloat162*)&qu.w);
            float r0 = fmaxf(v0.x + p01.x + q01.x + bi0.x, 0.f);
            float r1 = fmaxf(v0.y + p01.y + q01.y + bi0.y, 0.f);
            float r2 = fmaxf(v0.z + p23.x + q23.x + bi0.z, 0.f);
            float r3 = fmaxf(v0.w + p23.y + q23.y + bi0.w, 0.f);
            float r4 = fmaxf(v1.x + p45.x + q45.x + bi1.x, 0.f);
            float r5 = fmaxf(v1.y + p45.y + q45.y + bi1.y, 0.f);
            float r6 = fmaxf(v1.z + p67.x + q67.x + bi1.z, 0.f);
            float r7 = fmaxf(v1.w + p67.y + q67.y + bi1.w, 0.f);
            uint4 o;
            __nv_bfloat162 t2;
            t2 = __floats2bfloat162_rn(r0, r1); o.x = *(uint32_t*)&t2;
            t2 = __floats2bfloat162_rn(r2, r3); o.y = *(uint32_t*)&t2;
            t2 = __floats2bfloat162_rn(r4, r5); o.z = *(uint32_t*)&t2;
            t2 = __floats2bfloat162_rn(r6, r7); o.w = *(uint32_t*)&t2;
            *(uint4*)(fused + (size_t)(e0 + e) * 1024 + jc) = o;
            __syncwarp();
        }
    }
}

// ===== k_hdn: 4 warps, warp tile 64x64 ======================================
#define H_AS 0
#define H_BS 36864
#define H_TOTAL 71680

__global__ __launch_bounds__(128, 2) void k_hdn(
    const __nv_bfloat16* __restrict__ fused, const __nv_bfloat16* __restrict__ Wf1H,
    const float* __restrict__ bf1, const float* __restrict__ Wf2,
    float* __restrict__ logit) {
    extern __shared__ char sm[];
    uint32_t smb = smem_u32(sm);
    __nv_bfloat16* As = (__nv_bfloat16*)(sm + H_AS);
    __nv_bfloat16* Bs = (__nv_bfloat16*)(sm + H_BS);

    int tid = threadIdx.x, w = tid >> 5, lane = tid & 31;
    int n0 = blockIdx.x * 128, e0 = blockIdx.y * 128;
    int wm = w & 1, wn = w >> 1;

    auto stage = [&](int s) {
        int kc = s * 64, buf = s & 1;
#pragma unroll
        for (int i = tid; i < 1024; i += 128) {
            int r = i >> 3, c = (i & 7) * 8;
            cpa16(smb + H_AS + (uint32_t)((buf * 128 + r) * 72 + c) * 2,
                  fused + (size_t)(e0 + r) * 1024 + kc + c);
        }
#pragma unroll
        for (int i = tid; i < 1024; i += 128) {
            int r = i >> 4, c = (i & 15) * 8;
            cpa16(smb + H_BS + (uint32_t)((buf * 64 + r) * 136 + c) * 2,
                  Wf1H + (size_t)(kc + r) * 512 + n0 + c);
        }
    };

    FragC acc[4][4];
#pragma unroll
    for (int mt = 0; mt < 4; mt++)
#pragma unroll
        for (int nt = 0; nt < 4; nt++) wmma::fill_fragment(acc[mt][nt], 0.f);

    stage(0); CP_COMMIT();
    for (int s = 0; s < 16; s++) {
        if (s + 1 < 16) { stage(s + 1); CP_COMMIT(); CP_WAIT1(); }
        else { CP_WAIT0(); }
        __syncthreads();
        const __nv_bfloat16* Ab = As + (s & 1) * 128 * 72;
        const __nv_bfloat16* Bb = Bs + (s & 1) * 64 * 136;
#pragma unroll
        for (int k16 = 0; k16 < 4; k16++) {
            FragA a[4];
#pragma unroll
            for (int mt = 0; mt < 4; mt++)
                wmma::load_matrix_sync(a[mt], Ab + (wm * 64 + mt * 16) * 72 + k16 * 16, 72);
#pragma unroll
            for (int nt = 0; nt < 4; nt++) {
                FragB b;
                wmma::load_matrix_sync(b, Bb + (k16 * 16) * 136 + wn * 64 + nt * 16, 136);
#pragma unroll
                for (int mt = 0; mt < 4; mt++)
                    wmma::mma_sync(acc[mt][nt], a[mt], b, acc[mt][nt]);
            }
        }
        __syncthreads();
    }

    float* wscr = (float*)(sm + H_AS) + w * 256;
    int r = lane >> 1, cb = (lane & 1) * 8;
#pragma unroll
    for (int mt = 0; mt < 4; mt++) {
        float part = 0.f;
#pragma unroll
        for (int nt = 0; nt < 4; nt++) {
            wmma::store_matrix_sync(wscr, acc[mt][nt], 16, wmma::mem_row_major);
            __syncwarp();
            int ncol = n0 + wn * 64 + nt * 16 + cb;
            float4 v0 = *(float4*)(wscr + r * 16 + cb);
            float4 v1 = *(float4*)(wscr + r * 16 + cb + 4);
            float4 b0 = *(const float4*)(bf1 + ncol);
            float4 b1 = *(const float4*)(bf1 + ncol + 4);
            float4 w0 = *(const float4*)(Wf2 + ncol);
            float4 w1 = *(const float4*)(Wf2 + ncol + 4);
            part += fmaxf(v0.x + b0.x, 0.f) * w0.x + fmaxf(v0.y + b0.y, 0.f) * w0.y +
                    fmaxf(v0.z + b0.z, 0.f) * w0.z + fmaxf(v0.w + b0.w, 0.f) * w0.w +
                    fmaxf(v1.x + b1.x, 0.f) * w1.x + fmaxf(v1.y + b1.y, 0.f) * w1.y +
                    fmaxf(v1.z + b1.z, 0.f) * w1.z + fmaxf(v1.w + b1.w, 0.f) * w1.w;
            __syncwarp();
        }
        part += __shfl_xor_sync(0xffffffffu, part, 1);
        if ((lane & 1) == 0)
            atomicAdd(&logit[e0 + wm * 64 + mt * 16 + r], part);
    }
}

// ---------------- sigmoid ----------------
__global__ void k_sigmoid(const float* __restrict__ logit, const float* __restrict__ bf2,
                          float* __restrict__ outp) {
    int i = blockIdx.x * blockDim.x + threadIdx.x;
    if (i < EE) outp[i] = 1.f / (1.f + expf(-(logit[i] + bf2[0])));
}

// ---------------- launch ----------------
extern "C" void kernel_launch(void* const* d_in, const int* in_sizes, int n_in,
                              void* d_out, int out_size) {
    const float* x = (const float*)d_in[0];
    const int* ei = (const int*)d_in[1];
    const float* local_emb = (const float*)d_in[2];
    const float* W1 = (const float*)d_in[3];
    const float* a_src1 = (const float*)d_in[4];
    const float* a_trg1 = (const float*)d_in[5];
    const float* b1 = (const float*)d_in[6];
    const float* W2 = (const float*)d_in[7];
    const float* a_src2 = (const float*)d_in[8];
    const float* a_trg2 = (const float*)d_in[9];
    const float* b2 = (const float*)d_in[10];
    const float* Wi = (const float*)d_in[11];
    const float* bi = (const float*)d_in[12];
    const float* Wf1 = (const float*)d_in[13];
    const float* bf1 = (const float*)d_in[14];
    const float* Wf2 = (const float*)d_in[15];
    const float* bf2 = (const float*)d_in[16];
    float* outp = (float*)d_out;

    void* tmp;
    float *p_ssrc1, *p_strg1, *p_ssrc2, *p_strg2, *p_logit;
    __half *p_proj1h, *p_proj2h, *p_hh, *p_w2h;
    __nv_bfloat16 *p_out2h, *p_PQh, *p_wacad, *p_wibh, *p_wf1h, *p_msh, *p_fused;
#define SYM(p, s) cudaGetSymbolAddress(&tmp, s); p = (decltype(p))tmp;
    SYM(p_proj1h, g_proj1h) SYM(p_ssrc1, g_ssrc1) SYM(p_strg1, g_strg1)
    SYM(p_hh, g_hh) SYM(p_w2h, g_w2h)
    SYM(p_proj2h, g_proj2h) SYM(p_ssrc2, g_ssrc2) SYM(p_strg2, g_strg2)
    SYM(p_logit, g_logit)
    SYM(p_out2h, g_out2h) SYM(p_PQh, g_PQh) SYM(p_wacad, g_wacad)
    SYM(p_wibh, g_wib_h) SYM(p_wf1h, g_wf1_h) SYM(p_msh, g_msh) SYM(p_fused, g_fused)
#undef SYM

    cudaFuncSetAttribute(k_gemm_tf32h<128, 256>,
                         cudaFuncAttributeMaxDynamicSharedMemorySize, TF32_SMEM);
    cudaFuncSetAttribute(k_fused, cudaFuncAttributeMaxDynamicSharedMemorySize, F_TOTAL);
    cudaFuncSetAttribute(k_hdn, cudaFuncAttributeMaxDynamicSharedMemorySize, H_TOTAL);

    const int EB = (EE + 255) / 256;

    k_init<<<256, 256>>>();
    k_wprep<<<1024, 256>>>(Wi, p_wacad, p_wibh);
    k_cvt_wf1<<<2048, 256>>>(Wf1, p_wf1h);
    k_cvt_w2<<<1024, 256>>>(W2, p_w2h);

    // ---- edge sort by target ----
    k_hist<<<EB, 256>>>(ei);
    k_scan<<<1, 1024>>>();
    k_sortE<<<EB, 256>>>(ei);

    // ---- GAT layer 1 ----
    k_gemm_tf32h<128, 256><<<dim3(NP / 128, 2), 256, TF32_SMEM>>>(x, W1, p_proj1h);
    k_scores<2><<<NN, 64>>>(p_proj1h, a_src1, a_trg1, p_ssrc1, p_strg1);
    k_agg1<<<(NN + 7) / 8, 256>>>(p_ssrc1, p_strg1, p_proj1h, local_emb, b1, p_hh);

    // ---- GAT layer 2 (fp16 HMMA) ----
    k_gemm_fp16<512, 512><<<dim3(NP / 128, 4), 256>>>(p_hh, p_w2h, p_proj2h);
    k_scores<4><<<NN, 128>>>(p_proj2h, a_src2, a_trg2, p_ssrc2, p_strg2);
    k_agg2<<<(NN + 7) / 8, 256>>>(p_ssrc2, p_strg2, p_proj2h, b2, p_out2h);

    // ---- P|Q combined bf16 GEMM ----
    k_gemm_bf16h<128, 2048><<<dim3(NP / 128, 16), 256>>>(p_out2h, p_wacad, p_PQh);

    // ---- edge MLP as dense GEMMs ----
    k_msh<<<EE / 8, 256>>>(ei, p_out2h, p_msh);
    k_fused<<<dim3(8, EE / 128), 128, F_TOTAL>>>(ei, p_msh, p_wibh, p_PQh, bi, p_fused);
    k_hdn<<<dim3(4, EE / 128), 128, H_TOTAL>>>(p_fused, p_wf1h, bf1, Wf2, p_logit);
    k_sigmoid<<<EB, 256>>>(p_logit, bf2, outp);
}